// round 10
// baseline (speedup 1.0000x reference)
#include <cuda_runtime.h>
#include <cuda_fp16.h>
#include <math.h>
#include <stdint.h>

// ============================================================================
// QuantizedSSM via mma.sync (HMMA) with chunked fp32 re-accumulation.
// HMMA internal accumulation rounds toward zero -> flush into a master fp32
// accumulator (RN) every 4 chunks (256 k-elements).
//   x_next = q8( x @ Aq^T + u @ Bq^T ) : fused fp16 GEMM, K = 6144
//   y      = q8( x_next @ Cq^T )       : exact fp16 GEMM, K = 2048
// R10: replace per-chunk __syncthreads with mbarrier full/empty producer-
//      consumer pipeline -> warps free-run up to NSTAGE chunks apart.
//      Config otherwise = R7 (128x64 tile, 2 CTAs/SM, 4 stages, 1-buf frags).
// ============================================================================

#define MDIM 4096
#define NDIM 2048
#define MMID 1024
#define KEFF (2*NDIM + 2*MMID)   // 6144

__device__ __half g_Aq [(size_t)NDIM * NDIM];
__device__ __half g_Aq2[(size_t)NDIM * NDIM];   // Aq / 64
__device__ __half g_Bq [(size_t)NDIM * MMID];
__device__ __half g_Bq2[(size_t)NDIM * MMID];   // Bq / 64
__device__ __half g_Cq [(size_t)MMID * NDIM];
__device__ __half g_XU [(size_t)MDIM * KEFF];   // [x1 | x2*64 | u1 | u2*64]
__device__ __half g_Xn [(size_t)MDIM * NDIM];   // x_next fp16 (exact)

// ----------------------------------------------------------------------------
// q8 = to_float8(v, 4, 3), branch-free bit version (exact vs reference).
// ----------------------------------------------------------------------------
__device__ __forceinline__ float q8(float v) {
    float a  = fabsf(v);
    float ae = a + 1e-8f;
    int e = ((__float_as_int(ae) >> 23) & 0xFF) - 127;
    e = min(max(e, -7), 7);
    float p  = __int_as_float((e + 127) << 23);   // 2^e
    float rp = __int_as_float((127 - e) << 23);   // 2^-e (exact)
    float m  = fmaf(a, rp, -1.0f);
    float mq = rintf(m * 8.0f);                   // round-half-even == jnp.round
    float r  = fmaf(mq, 0.125f, 1.0f) * p;
    return (v > 0.0f) ? r : ((v < 0.0f) ? -r : 0.0f);
}

// ----------------------------------------------------------------------------
// PTX helpers — all plain-target instructions (verified compiling on sm_103)
// ----------------------------------------------------------------------------
__device__ __forceinline__ uint32_t smem_u32(const void* p) {
    uint32_t a;
    asm("{ .reg .u64 t; cvta.to.shared.u64 t, %1; cvt.u32.u64 %0, t; }"
        : "=r"(a) : "l"(p));
    return a;
}
__device__ __forceinline__ bool elect_one() {
    uint32_t p;
    asm volatile("{ .reg .pred p; elect.sync _|p, 0xFFFFFFFF; selp.b32 %0,1,0,p; }"
                 : "=r"(p));
    return p != 0;
}
__device__ __forceinline__ void cp16(uint32_t dst, const void* src) {
    asm volatile("cp.async.cg.shared.global [%0], [%1], 16;"
                 :: "r"(dst), "l"(src) : "memory");
}
__device__ __forceinline__ void cp_commit() {
    asm volatile("cp.async.commit_group;" ::: "memory");
}
__device__ __forceinline__ void mbar_init(uint32_t mbar, uint32_t cnt) {
    asm volatile("mbarrier.init.shared.b64 [%0], %1;" :: "r"(mbar), "r"(cnt) : "memory");
}
__device__ __forceinline__ void mbar_arrive(uint32_t mbar) {
    asm volatile("mbarrier.arrive.shared.b64 _, [%0];" :: "r"(mbar) : "memory");
}
__device__ __forceinline__ void mbar_wait(uint32_t mbar, uint32_t parity) {
    asm volatile(
        "{ .reg .pred P;\n"
        "W_%=: mbarrier.try_wait.parity.acquire.cta.shared::cta.b64 P, [%0], %1, 0x989680;\n"
        "@P bra D_%=;\n"
        "bra W_%=;\n"
        "D_%=: }\n"
        :: "r"(mbar), "r"(parity) : "memory");
}
__device__ __forceinline__ void ldsm4(uint32_t& r0, uint32_t& r1, uint32_t& r2,
                                      uint32_t& r3, uint32_t addr) {
    asm volatile("ldmatrix.sync.aligned.m8n8.x4.shared.b16 {%0,%1,%2,%3}, [%4];"
                 : "=r"(r0), "=r"(r1), "=r"(r2), "=r"(r3) : "r"(addr));
}
__device__ __forceinline__ void mma16816(float* d, const uint32_t* a, const uint32_t* b) {
    asm volatile(
        "mma.sync.aligned.m16n8k16.row.col.f32.f16.f16.f32 "
        "{%0,%1,%2,%3}, {%4,%5,%6,%7}, {%8,%9}, {%0,%1,%2,%3};"
        : "+f"(d[0]), "+f"(d[1]), "+f"(d[2]), "+f"(d[3])
        : "r"(a[0]), "r"(a[1]), "r"(a[2]), "r"(a[3]), "r"(b[0]), "r"(b[1]));
}

// SW128 swizzle (Swizzle<3,4,3>) on byte offsets within a 128B-row tile
__device__ __forceinline__ uint32_t swz(uint32_t o) { return o ^ ((o >> 3) & 0x70); }

// ----------------------------------------------------------------------------
// Prep kernels
// ----------------------------------------------------------------------------
#define NA (NDIM*NDIM)
#define NB (NDIM*MMID)
#define NC (MMID*NDIM)
__global__ void quantW(const float* __restrict__ A, const float* __restrict__ B,
                       const float* __restrict__ C,
                       __half* __restrict__ Aq, __half* __restrict__ Aq2,
                       __half* __restrict__ Bq, __half* __restrict__ Bq2,
                       __half* __restrict__ Cq)
{
    size_t i = ((size_t)blockIdx.x * blockDim.x + threadIdx.x) * 4;
    const float* in; __half *o1, *o2;
    if (i < NA)                { in = A + i;            o1 = Aq + i;  o2 = Aq2 + i; }
    else if (i < NA + NB)      { i -= NA; in = B + i;   o1 = Bq + i;  o2 = Bq2 + i; }
    else if (i < NA + NB + NC) { i -= NA + NB; in = C + i; o1 = Cq + i; o2 = nullptr; }
    else return;

    float4 v = *reinterpret_cast<const float4*>(in);
    float q0 = q8(v.x), q1 = q8(v.y), q2 = q8(v.z), q3 = q8(v.w);
    __half2 p0 = __floats2half2_rn(q0, q1);
    __half2 p1 = __floats2half2_rn(q2, q3);
    uint2 pk;
    pk.x = *reinterpret_cast<uint32_t*>(&p0);
    pk.y = *reinterpret_cast<uint32_t*>(&p1);
    *reinterpret_cast<uint2*>(o1) = pk;
    if (o2) {
        const float s = 0.015625f;  // 1/64, exact scaling
        __half2 s0 = __floats2half2_rn(q0 * s, q1 * s);
        __half2 s1 = __floats2half2_rn(q2 * s, q3 * s);
        uint2 sk;
        sk.x = *reinterpret_cast<uint32_t*>(&s0);
        sk.y = *reinterpret_cast<uint32_t*>(&s1);
        *reinterpret_cast<uint2*>(o2) = sk;
    }
}

// split fp32 -> plane1 = fp16(v) at [col], plane2 = fp16((v-plane1)*64) at [col+cols]
__global__ void splitk(const float* __restrict__ src, int cols, __half* __restrict__ dst) {
    size_t idx = (size_t)blockIdx.x * blockDim.x + threadIdx.x;
    size_t i4 = idx * 4;
    if (i4 >= (size_t)MDIM * cols) return;
    int row = (int)(i4 / cols);
    int col = (int)(i4 % cols);
    float4 v = *reinterpret_cast<const float4*>(src + i4);
    float f[4] = {v.x, v.y, v.z, v.w};
    __half h1[4], h2[4];
#pragma unroll
    for (int j = 0; j < 4; j++) {
        __half b1 = __float2half_rn(f[j]);
        float r1 = f[j] - __half2float(b1);   // exact in fp32
        h1[j] = b1;
        h2[j] = __float2half_rn(r1 * 64.0f);  // scaled into normal fp16 range
    }
    __half* d0 = dst + (size_t)row * KEFF + col;
    auto pack = [](__half* h) {
        __half2 p0(h[0], h[1]), p1(h[2], h[3]);
        uint2 r;
        r.x = *reinterpret_cast<uint32_t*>(&p0);
        r.y = *reinterpret_cast<uint32_t*>(&p1);
        return r;
    };
    *reinterpret_cast<uint2*>(d0)        = pack(h1);
    *reinterpret_cast<uint2*>(d0 + cols) = pack(h2);
}

// ----------------------------------------------------------------------------
// HMMA GEMM-NT, 128x64 CTA tile, BK=64, 4-stage mbarrier pipeline (no CTA-wide
// barriers in the mainloop). Warps free-run up to NSTAGE chunks apart.
// Per chunk c, stage s=c%4, each warp:
//   wait empty[(c+3)%4] -> load chunk c+3 -> commit -> wait_group 3 (own cps of
//   chunk c complete) -> elected arrive full[s] -> wait full[s] -> compute ->
//   elected arrive empty[s].
// MODE 0 (fused GEMM1): chunk c -> B segment
//   c in [ 0,32): Aq   col (c&31)*64, ld NDIM   (pairs x plane1)
//   c in [32,64): Aq2  col (c&31)*64, ld NDIM   (pairs x plane2)
//   c in [64,80): Bq   col (c&15)*64, ld MMID   (pairs u plane1)
//   c in [80,96): Bq2  col (c&15)*64, ld MMID   (pairs u plane2)
//   epilogue: q8 -> fp32 outp + fp16 aux
// MODE 1 (GEMM2): B = P0 col (c&31)*64, ld NDIM; epilogue q8 -> fp32 outp.
// nchunk must be a multiple of 4 (96 and 32 are).
// ----------------------------------------------------------------------------
#define NSTAGE 4
#define BKE 64
#define TILEM 128
#define TILEN 64
#define A_BYTES (TILEM * 128)                   // 16 KB
#define B_BYTES (TILEN * 128)                   //  8 KB
#define STAGE_BYTES (A_BYTES + B_BYTES)         // 24 KB
#define SMEM_CTRL 64
#define SMEM_SZ (SMEM_CTRL + NSTAGE * STAGE_BYTES)   // 98368

template <int MODE>
__global__ void __launch_bounds__(256, 2)
mma_gemm(const __half* __restrict__ Aop, int ldA, int nchunk,
         const __half* __restrict__ P0, const __half* __restrict__ P1,
         const __half* __restrict__ P2, const __half* __restrict__ P3,
         float* __restrict__ outp, __half* __restrict__ aux, int ldOut)
{
    extern __shared__ char smem[];
    const uint32_t sb = smem_u32(smem);
    const int tid  = threadIdx.x;
    const int lane = tid & 31;
    const int wid  = tid >> 5;
    const int wm   = wid & 3;    // 4 m-slices of 32
    const int wn   = wid >> 2;   // 2 n-slices of 32
    const int m0 = blockIdx.y * TILEM;
    const int n0 = blockIdx.x * TILEN;

    // mbarriers: full[s] = sb + 8s, empty[s] = sb + 32 + 8s  (count = 8 warps)
    if (tid == 0) {
#pragma unroll
        for (int s = 0; s < NSTAGE; s++) {
            mbar_init(sb + 8 * s, 8);
            mbar_init(sb + 32 + 8 * s, 8);
        }
    }
    __syncthreads();   // once, for mbarrier init visibility

    // A: 128 rows, 2 threads/row, 4 x 16B each.  B: 64 rows, 4 threads/row, 2 x 16B.
    const int alr  = tid >> 1;
    const int alc0 = (tid & 1) * 4;
    const int blr  = tid >> 2;
    const int blc0 = (tid & 3) * 2;

    auto load_chunk = [&](int c) {
        const uint32_t sA = sb + SMEM_CTRL + (c % NSTAGE) * STAGE_BYTES;
        const uint32_t sB = sA + A_BYTES;
        const __half* arow = Aop + (size_t)(m0 + alr) * ldA + c * BKE;
        const __half* bsrc; int ldB;
        if (MODE == 0) {
            if (c < 64) { bsrc = ((c < 32) ? P0 : P1) + (size_t)(c & 31) * BKE; ldB = NDIM; }
            else        { bsrc = ((c < 80) ? P2 : P3) + (size_t)(c & 15) * BKE; ldB = MMID; }
        } else {
            bsrc = P0 + (size_t)(c & 31) * BKE; ldB = NDIM;
        }
        const __half* brow = bsrc + (size_t)(n0 + blr) * ldB;
#pragma unroll
        for (int j = 0; j < 4; j++) {
            int c16 = alc0 + j;
            cp16(sA + swz(alr * 128 + c16 * 16), arow + c16 * 8);
        }
#pragma unroll
        for (int j = 0; j < 2; j++) {
            int c16 = blc0 + j;
            cp16(sB + swz(blr * 128 + c16 * 16), brow + c16 * 8);
        }
        cp_commit();
    };

    float mst[2][4][4];   // master fp32 accumulator (RN adds)
    float acc[2][4][4];   // HMMA chain accumulator (short chains only)
#pragma unroll
    for (int i = 0; i < 2; i++)
#pragma unroll
        for (int j = 0; j < 4; j++)
#pragma unroll
            for (int k = 0; k < 4; k++) mst[i][j][k] = 0.0f;

    const int arow_lo = wm * 32 + ((lane >> 3) & 1) * 8 + (lane & 7);  // + mt*16
    const int aku_off = (lane >> 4);                                    // + ks*2
    const int brow_lo = wn * 32 + (lane >> 4) * 8 + (lane & 7);         // + np*16
    const int bku_off = ((lane >> 3) & 1);                              // + ks*2

    auto compute_chunk = [&](uint32_t sA, uint32_t sB) {
#pragma unroll
        for (int ks = 0; ks < 4; ks++) {        // 4 x k16 per 64-chunk
            uint32_t af[2][4];
#pragma unroll
            for (int mt = 0; mt < 2; mt++) {
                int row = arow_lo + mt * 16;
                int ku  = ks * 2 + aku_off;
                ldsm4(af[mt][0], af[mt][1], af[mt][2], af[mt][3],
                      sA + swz(row * 128 + ku * 16));
            }
            uint32_t bf[2][4];
#pragma unroll
            for (int np = 0; np < 2; np++) {
                int row = brow_lo + np * 16;
                int ku  = ks * 2 + bku_off;
                ldsm4(bf[np][0], bf[np][1], bf[np][2], bf[np][3],
                      sB + swz(row * 128 + ku * 16));
            }
#pragma unroll
            for (int mt = 0; mt < 2; mt++)
#pragma unroll
                for (int nt = 0; nt < 4; nt++)
                    mma16816(acc[mt][nt], af[mt], &bf[nt >> 1][(nt & 1) * 2]);
        }
    };

    // prologue: chunks 0..2 (no empty-wait needed; stages fresh)
    load_chunk(0);
    load_chunk(1);
    load_chunk(2);

    for (int c = 0; c < nchunk; c++) {
        const int s = c % NSTAGE;

        // produce chunk c+3 (stage (c+3)%4): wait for it to be consumed first
        const int cc = c + 3;
        if (cc < nchunk) {
            if (cc >= NSTAGE)
                mbar_wait(sb + 32 + 8 * (cc % NSTAGE), (uint32_t)(((cc >> 2) + 1) & 1));
            load_chunk(cc);
        } else {
            cp_commit();   // keep per-warp group numbering uniform
        }

        // own cps for chunk c (committed 3 groups ago) must be done
        asm volatile("cp.async.wait_group 3;" ::: "memory");
        if (elect_one()) mbar_arrive(sb + 8 * s);          // full[s] arrive

        // consume chunk c once all 8 warps' data has landed
        mbar_wait(sb + 8 * s, (uint32_t)((c >> 2) & 1));    // full[s] wait

        if ((c & 3) == 0) {                      // start fresh HMMA chain
#pragma unroll
            for (int i = 0; i < 2; i++)
#pragma unroll
                for (int j = 0; j < 4; j++)
#pragma unroll
                    for (int k = 0; k < 4; k++) acc[i][j][k] = 0.0f;
        }

        const uint32_t sA = sb + SMEM_CTRL + s * STAGE_BYTES;
        compute_chunk(sA, sA + A_BYTES);

        if (elect_one()) mbar_arrive(sb + 32 + 8 * s);      // empty[s] arrive

        if ((c & 3) == 3) {                      // flush chain into master (RN)
#pragma unroll
            for (int i = 0; i < 2; i++)
#pragma unroll
                for (int j = 0; j < 4; j++)
#pragma unroll
                    for (int k = 0; k < 4; k++) mst[i][j][k] += acc[i][j][k];
        }
    }

    // Epilogue: q8 then direct stores
#pragma unroll
    for (int mt = 0; mt < 2; mt++) {
#pragma unroll
        for (int nt = 0; nt < 4; nt++) {
            int row0 = m0 + wm * 32 + mt * 16 + (lane >> 2);
            int col  = n0 + wn * 32 + nt * 8 + 2 * (lane & 3);
#pragma unroll
            for (int h = 0; h < 2; h++) {
                int row = row0 + h * 8;
                float v0 = q8(mst[mt][nt][h * 2 + 0]);
                float v1 = q8(mst[mt][nt][h * 2 + 1]);
                size_t g = (size_t)row * ldOut + col;
                *reinterpret_cast<float2*>(outp + g) = make_float2(v0, v1);
                if (MODE == 0) {
                    __half2 hv = __floats2half2_rn(v0, v1);
                    *reinterpret_cast<__half2*>(aux + g) = hv;
                }
            }
        }
    }
}

// ----------------------------------------------------------------------------
// Host launcher
// Launch order (ncu -s capture at index 3 = mma_gemm<0>):
//   0: quantW   1: splitk(x)   2: splitk(u)   3: gemm1   4: gemm2
// ----------------------------------------------------------------------------
extern "C" void kernel_launch(void* const* d_in, const int* in_sizes, int n_in,
                              void* d_out, int out_size)
{
    const float* x = (const float*)d_in[0];
    const float* u = (const float*)d_in[1];
    const float* A = (const float*)d_in[2];
    const float* B = (const float*)d_in[3];
    const float* C = (const float*)d_in[4];

    float* x_next = (float*)d_out;
    float* y      = (float*)d_out + (size_t)MDIM * NDIM;

    __half *Aq, *Aq2, *Bq, *Bq2, *Cq, *XU, *Xn;
    cudaGetSymbolAddress((void**)&Aq,  g_Aq);
    cudaGetSymbolAddress((void**)&Aq2, g_Aq2);
    cudaGetSymbolAddress((void**)&Bq,  g_Bq);
    cudaGetSymbolAddress((void**)&Bq2, g_Bq2);
    cudaGetSymbolAddress((void**)&Cq,  g_Cq);
    cudaGetSymbolAddress((void**)&XU,  g_XU);
    cudaGetSymbolAddress((void**)&Xn,  g_Xn);

    cudaFuncSetAttribute(mma_gemm<0>, cudaFuncAttributeMaxDynamicSharedMemorySize, SMEM_SZ);
    cudaFuncSetAttribute(mma_gemm<1>, cudaFuncAttributeMaxDynamicSharedMemorySize, SMEM_SZ);

    const int T = 256;
    // 0: all weight quantization in one launch
    {
        int total4 = (NA + NB + NC) / 4;
        quantW<<<(total4 + T - 1) / T, T>>>(A, B, C, Aq, Aq2, Bq, Bq2, Cq);
    }
    // 1-2: activation splits
    splitk<<<(int)(((size_t)MDIM * NDIM / 4 + T - 1) / T), T>>>(x, NDIM, XU);
    splitk<<<(int)(((size_t)MDIM * MMID / 4 + T - 1) / T), T>>>(u, MMID, XU + 2 * NDIM);

    // 3: fused GEMM1: x_next = q8(XU @ [Aq | Aq/64 | Bq | Bq/64]^T), K=6144
    {
        dim3 grid(NDIM / TILEN, MDIM / TILEM);   // (32, 32)
        mma_gemm<0><<<grid, 256, SMEM_SZ>>>(
            XU, KEFF, KEFF / BKE,
            Aq, Aq2, Bq, Bq2,
            x_next, Xn, NDIM);
    }
    // 4: GEMM2: y = q8(Xn @ Cq^T), K=2048
    {
        dim3 grid(MMID / TILEN, MDIM / TILEM);   // (16, 32)
        mma_gemm<1><<<grid, 256, SMEM_SZ>>>(
            Xn, NDIM, NDIM / BKE,
            Cq, (const __half*)nullptr, (const __half*)nullptr, (const __half*)nullptr,
            y, (__half*)nullptr, MMID);
    }
}

// round 11
// speedup vs baseline: 1.3308x; 1.3308x over previous
#include <cuda_runtime.h>
#include <cuda_fp16.h>
#include <math.h>
#include <stdint.h>

// ============================================================================
// QuantizedSSM via mma.sync (HMMA) with chunked fp32 re-accumulation.
// HMMA internal accumulation rounds toward zero -> flush into a master fp32
// accumulator (RN) every 4 chunks (256 k-elements).
//   x_next = q8( x @ Aq^T + u @ Bq^T ) : fused fp16 GEMM, K = 6144
//   y      = q8( x_next @ Cq^T )       : exact fp16 GEMM, K = 2048
// R11 (base = R8: 128x64 tile, 2 CTAs/SM, 4 stages, dbuf frags, syncthreads):
//   - wait_group 1: chunks c AND c+1 resident after each barrier
//   - cross-chunk frag prefetch: (c+1, ks0) loaded during (c, ks3) MMAs so
//     MMAs issue immediately after the barrier (kills the ldsm-latency convoy)
//   - cp.async.ca for A (activations shared with the co-resident CTA)
// ============================================================================

#define MDIM 4096
#define NDIM 2048
#define MMID 1024
#define KEFF (2*NDIM + 2*MMID)   // 6144

__device__ __half g_Aq [(size_t)NDIM * NDIM];
__device__ __half g_Aq2[(size_t)NDIM * NDIM];   // Aq / 64
__device__ __half g_Bq [(size_t)NDIM * MMID];
__device__ __half g_Bq2[(size_t)NDIM * MMID];   // Bq / 64
__device__ __half g_Cq [(size_t)MMID * NDIM];
__device__ __half g_XU [(size_t)MDIM * KEFF];   // [x1 | x2*64 | u1 | u2*64]
__device__ __half g_Xn [(size_t)MDIM * NDIM];   // x_next fp16 (exact)

// ----------------------------------------------------------------------------
// q8 = to_float8(v, 4, 3), branch-free bit version (exact vs reference).
// ----------------------------------------------------------------------------
__device__ __forceinline__ float q8(float v) {
    float a  = fabsf(v);
    float ae = a + 1e-8f;
    int e = ((__float_as_int(ae) >> 23) & 0xFF) - 127;
    e = min(max(e, -7), 7);
    float p  = __int_as_float((e + 127) << 23);   // 2^e
    float rp = __int_as_float((127 - e) << 23);   // 2^-e (exact)
    float m  = fmaf(a, rp, -1.0f);
    float mq = rintf(m * 8.0f);                   // round-half-even == jnp.round
    float r  = fmaf(mq, 0.125f, 1.0f) * p;
    return (v > 0.0f) ? r : ((v < 0.0f) ? -r : 0.0f);
}

// ----------------------------------------------------------------------------
// PTX helpers — all plain-target (sm_80+) instructions
// ----------------------------------------------------------------------------
__device__ __forceinline__ uint32_t smem_u32(const void* p) {
    uint32_t a;
    asm("{ .reg .u64 t; cvta.to.shared.u64 t, %1; cvt.u32.u64 %0, t; }"
        : "=r"(a) : "l"(p));
    return a;
}
__device__ __forceinline__ void cp16(uint32_t dst, const void* src) {
    asm volatile("cp.async.cg.shared.global [%0], [%1], 16;"
                 :: "r"(dst), "l"(src) : "memory");
}
__device__ __forceinline__ void cp16_ca(uint32_t dst, const void* src) {
    asm volatile("cp.async.ca.shared.global [%0], [%1], 16;"
                 :: "r"(dst), "l"(src) : "memory");
}
__device__ __forceinline__ void cp_commit() {
    asm volatile("cp.async.commit_group;" ::: "memory");
}
__device__ __forceinline__ void ldsm4(uint32_t& r0, uint32_t& r1, uint32_t& r2,
                                      uint32_t& r3, uint32_t addr) {
    asm volatile("ldmatrix.sync.aligned.m8n8.x4.shared.b16 {%0,%1,%2,%3}, [%4];"
                 : "=r"(r0), "=r"(r1), "=r"(r2), "=r"(r3) : "r"(addr));
}
__device__ __forceinline__ void mma16816(float* d, const uint32_t* a, const uint32_t* b) {
    asm volatile(
        "mma.sync.aligned.m16n8k16.row.col.f32.f16.f16.f32 "
        "{%0,%1,%2,%3}, {%4,%5,%6,%7}, {%8,%9}, {%0,%1,%2,%3};"
        : "+f"(d[0]), "+f"(d[1]), "+f"(d[2]), "+f"(d[3])
        : "r"(a[0]), "r"(a[1]), "r"(a[2]), "r"(a[3]), "r"(b[0]), "r"(b[1]));
}

// SW128 swizzle (Swizzle<3,4,3>) on byte offsets within a 128B-row tile
__device__ __forceinline__ uint32_t swz(uint32_t o) { return o ^ ((o >> 3) & 0x70); }

// ----------------------------------------------------------------------------
// Prep kernels
// ----------------------------------------------------------------------------
#define NA (NDIM*NDIM)
#define NB (NDIM*MMID)
#define NC (MMID*NDIM)
__global__ void quantW(const float* __restrict__ A, const float* __restrict__ B,
                       const float* __restrict__ C,
                       __half* __restrict__ Aq, __half* __restrict__ Aq2,
                       __half* __restrict__ Bq, __half* __restrict__ Bq2,
                       __half* __restrict__ Cq)
{
    size_t i = ((size_t)blockIdx.x * blockDim.x + threadIdx.x) * 4;
    const float* in; __half *o1, *o2;
    if (i < NA)                { in = A + i;            o1 = Aq + i;  o2 = Aq2 + i; }
    else if (i < NA + NB)      { i -= NA; in = B + i;   o1 = Bq + i;  o2 = Bq2 + i; }
    else if (i < NA + NB + NC) { i -= NA + NB; in = C + i; o1 = Cq + i; o2 = nullptr; }
    else return;

    float4 v = *reinterpret_cast<const float4*>(in);
    float q0 = q8(v.x), q1 = q8(v.y), q2 = q8(v.z), q3 = q8(v.w);
    __half2 p0 = __floats2half2_rn(q0, q1);
    __half2 p1 = __floats2half2_rn(q2, q3);
    uint2 pk;
    pk.x = *reinterpret_cast<uint32_t*>(&p0);
    pk.y = *reinterpret_cast<uint32_t*>(&p1);
    *reinterpret_cast<uint2*>(o1) = pk;
    if (o2) {
        const float s = 0.015625f;  // 1/64, exact scaling
        __half2 s0 = __floats2half2_rn(q0 * s, q1 * s);
        __half2 s1 = __floats2half2_rn(q2 * s, q3 * s);
        uint2 sk;
        sk.x = *reinterpret_cast<uint32_t*>(&s0);
        sk.y = *reinterpret_cast<uint32_t*>(&s1);
        *reinterpret_cast<uint2*>(o2) = sk;
    }
}

// split fp32 -> plane1 = fp16(v) at [col], plane2 = fp16((v-plane1)*64) at [col+cols]
__global__ void splitk(const float* __restrict__ src, int cols, __half* __restrict__ dst) {
    size_t idx = (size_t)blockIdx.x * blockDim.x + threadIdx.x;
    size_t i4 = idx * 4;
    if (i4 >= (size_t)MDIM * cols) return;
    int row = (int)(i4 / cols);
    int col = (int)(i4 % cols);
    float4 v = *reinterpret_cast<const float4*>(src + i4);
    float f[4] = {v.x, v.y, v.z, v.w};
    __half h1[4], h2[4];
#pragma unroll
    for (int j = 0; j < 4; j++) {
        __half b1 = __float2half_rn(f[j]);
        float r1 = f[j] - __half2float(b1);   // exact in fp32
        h1[j] = b1;
        h2[j] = __float2half_rn(r1 * 64.0f);  // scaled into normal fp16 range
    }
    __half* d0 = dst + (size_t)row * KEFF + col;
    auto pack = [](__half* h) {
        __half2 p0(h[0], h[1]), p1(h[2], h[3]);
        uint2 r;
        r.x = *reinterpret_cast<uint32_t*>(&p0);
        r.y = *reinterpret_cast<uint32_t*>(&p1);
        return r;
    };
    *reinterpret_cast<uint2*>(d0)        = pack(h1);
    *reinterpret_cast<uint2*>(d0 + cols) = pack(h2);
}

// ----------------------------------------------------------------------------
// HMMA GEMM-NT, 128x64 CTA tile, BK=64, 4-stage single-chunk pipeline,
// double-buffered ldmatrix fragments WITH cross-chunk ks0 prefetch.
// 8 warps: wm = wid&3 (4 x 32 rows), wn = wid>>2 (2 x 32 cols).
// MODE 0 (fused GEMM1): chunk c -> B segment
//   c in [ 0,32): Aq   col (c&31)*64, ld NDIM   (pairs x plane1)
//   c in [32,64): Aq2  col (c&31)*64, ld NDIM   (pairs x plane2)
//   c in [64,80): Bq   col (c&15)*64, ld MMID   (pairs u plane1)
//   c in [80,96): Bq2  col (c&15)*64, ld MMID   (pairs u plane2)
//   epilogue: q8 -> fp32 outp + fp16 aux
// MODE 1 (GEMM2): B = P0 col (c&31)*64, ld NDIM; epilogue q8 -> fp32 outp.
// nchunk must be a multiple of 4 (96 and 32 are).
// ----------------------------------------------------------------------------
#define NSTAGE 4
#define BKE 64
#define TILEM 128
#define TILEN 64
#define A_BYTES (TILEM * 128)                   // 16 KB
#define B_BYTES (TILEN * 128)                   //  8 KB
#define STAGE_BYTES (A_BYTES + B_BYTES)         // 24 KB
#define SMEM_SZ (NSTAGE * STAGE_BYTES)          // 96 KB

template <int MODE>
__global__ void __launch_bounds__(256, 2)
mma_gemm(const __half* __restrict__ Aop, int ldA, int nchunk,
         const __half* __restrict__ P0, const __half* __restrict__ P1,
         const __half* __restrict__ P2, const __half* __restrict__ P3,
         float* __restrict__ outp, __half* __restrict__ aux, int ldOut)
{
    extern __shared__ char smem[];
    const uint32_t sb = smem_u32(smem);
    const int tid  = threadIdx.x;
    const int lane = tid & 31;
    const int wid  = tid >> 5;
    const int wm   = wid & 3;    // 4 m-slices of 32
    const int wn   = wid >> 2;   // 2 n-slices of 32
    const int m0 = blockIdx.y * TILEM;
    const int n0 = blockIdx.x * TILEN;

    // A: 128 rows, 2 threads/row, 4 x 16B each.  B: 64 rows, 4 threads/row, 2 x 16B.
    const int alr  = tid >> 1;
    const int alc0 = (tid & 1) * 4;
    const int blr  = tid >> 2;
    const int blc0 = (tid & 3) * 2;

    auto load_chunk = [&](int c) {
        const uint32_t sA = sb + (c % NSTAGE) * STAGE_BYTES;
        const uint32_t sB = sA + A_BYTES;
        const __half* arow = Aop + (size_t)(m0 + alr) * ldA + c * BKE;
        const __half* bsrc; int ldB;
        if (MODE == 0) {
            if (c < 64) { bsrc = ((c < 32) ? P0 : P1) + (size_t)(c & 31) * BKE; ldB = NDIM; }
            else        { bsrc = ((c < 80) ? P2 : P3) + (size_t)(c & 15) * BKE; ldB = MMID; }
        } else {
            bsrc = P0 + (size_t)(c & 31) * BKE; ldB = NDIM;
        }
        const __half* brow = bsrc + (size_t)(n0 + blr) * ldB;
#pragma unroll
        for (int j = 0; j < 4; j++) {
            int c16 = alc0 + j;
            cp16_ca(sA + swz(alr * 128 + c16 * 16), arow + c16 * 8);   // A: .ca (co-CTA reuse)
        }
#pragma unroll
        for (int j = 0; j < 2; j++) {
            int c16 = blc0 + j;
            cp16(sB + swz(blr * 128 + c16 * 16), brow + c16 * 8);      // B: .cg
        }
        cp_commit();
    };

    float mst[2][4][4];   // master fp32 accumulator (RN adds)
    float acc[2][4][4];   // HMMA chain accumulator (short chains only)
#pragma unroll
    for (int i = 0; i < 2; i++)
#pragma unroll
        for (int j = 0; j < 4; j++)
#pragma unroll
            for (int k = 0; k < 4; k++) mst[i][j][k] = 0.0f;

    // fragment double buffers
    uint32_t af[2][2][4];   // [buf][mt][reg]
    uint32_t bf[2][2][4];   // [buf][np][reg]

    // per-thread ldsm base rows
    const int arow_lo = wm * 32 + ((lane >> 3) & 1) * 8 + (lane & 7);  // + mt*16
    const int aku_off = (lane >> 4);                                    // + ks*2
    const int brow_lo = wn * 32 + (lane >> 4) * 8 + (lane & 7);         // + np*16
    const int bku_off = ((lane >> 3) & 1);                              // + ks*2

    auto load_frags = [&](uint32_t sA, uint32_t sB, int ks, int buf) {
#pragma unroll
        for (int mt = 0; mt < 2; mt++) {
            int row = arow_lo + mt * 16;
            int ku  = ks * 2 + aku_off;
            ldsm4(af[buf][mt][0], af[buf][mt][1], af[buf][mt][2], af[buf][mt][3],
                  sA + swz(row * 128 + ku * 16));
        }
#pragma unroll
        for (int np = 0; np < 2; np++) {
            int row = brow_lo + np * 16;
            int ku  = ks * 2 + bku_off;
            ldsm4(bf[buf][np][0], bf[buf][np][1], bf[buf][np][2], bf[buf][np][3],
                  sB + swz(row * 128 + ku * 16));
        }
    };

    // prologue
    load_chunk(0);
    load_chunk(1);
    load_chunk(2);
    asm volatile("cp.async.wait_group 1;" ::: "memory");   // chunks 0,1 resident
    __syncthreads();
    {   // preload (chunk 0, ks0) into buf 0
        const uint32_t sA0 = sb + 0 * STAGE_BYTES;
        load_frags(sA0, sA0 + A_BYTES, 0, 0);
    }

    for (int c = 0; c < nchunk; c++) {
        const int s = c % NSTAGE;

        if (c > 0) {
            // chunks c and c+1 resident & (after barrier) CTA-visible
            asm volatile("cp.async.wait_group 1;" ::: "memory");
            __syncthreads();
        }

        if (c + 3 < nchunk) load_chunk(c + 3);
        else                cp_commit();        // keep group accounting uniform

        const uint32_t sA = sb + s * STAGE_BYTES;
        const uint32_t sB = sA + A_BYTES;

        if ((c & 3) == 0) {                      // start fresh HMMA chain
#pragma unroll
            for (int i = 0; i < 2; i++)
#pragma unroll
                for (int j = 0; j < 4; j++)
#pragma unroll
                    for (int k = 0; k < 4; k++) acc[i][j][k] = 0.0f;
        }

        // buf (0) holds (c, ks0) on loop entry; MMAs issue immediately.
        // ks<3: prefetch (c, ks+1); ks==3: prefetch (c+1, ks0) — its stage is
        // resident (wait_group 1) and distinct from the stage load_chunk is
        // writing ((c+3)%4 == (c-1)%4 != (c+1)%4).
#pragma unroll
        for (int ks = 0; ks < 4; ks++) {
            const int cur = ks & 1, nxt = cur ^ 1;
            if (ks < 3) {
                load_frags(sA, sB, ks + 1, nxt);
            } else if (c + 1 < nchunk) {
                const uint32_t sA1 = sb + ((c + 1) % NSTAGE) * STAGE_BYTES;
                load_frags(sA1, sA1 + A_BYTES, 0, nxt);
            }
#pragma unroll
            for (int mt = 0; mt < 2; mt++)
#pragma unroll
                for (int nt = 0; nt < 4; nt++)
                    mma16816(acc[mt][nt], af[cur][mt], &bf[cur][nt >> 1][(nt & 1) * 2]);
        }

        if ((c & 3) == 3) {                      // flush chain into master (RN)
#pragma unroll
            for (int i = 0; i < 2; i++)
#pragma unroll
                for (int j = 0; j < 4; j++)
#pragma unroll
                    for (int k = 0; k < 4; k++) mst[i][j][k] += acc[i][j][k];
        }
    }

    // Epilogue: q8 then direct stores
#pragma unroll
    for (int mt = 0; mt < 2; mt++) {
#pragma unroll
        for (int nt = 0; nt < 4; nt++) {
            int row0 = m0 + wm * 32 + mt * 16 + (lane >> 2);
            int col  = n0 + wn * 32 + nt * 8 + 2 * (lane & 3);
#pragma unroll
            for (int h = 0; h < 2; h++) {
                int row = row0 + h * 8;
                float v0 = q8(mst[mt][nt][h * 2 + 0]);
                float v1 = q8(mst[mt][nt][h * 2 + 1]);
                size_t g = (size_t)row * ldOut + col;
                *reinterpret_cast<float2*>(outp + g) = make_float2(v0, v1);
                if (MODE == 0) {
                    __half2 hv = __floats2half2_rn(v0, v1);
                    *reinterpret_cast<__half2*>(aux + g) = hv;
                }
            }
        }
    }
}

// ----------------------------------------------------------------------------
// Host launcher
// Launch order (ncu -s capture at index 3 = mma_gemm<0>):
//   0: quantW   1: splitk(x)   2: splitk(u)   3: gemm1   4: gemm2
// ----------------------------------------------------------------------------
extern "C" void kernel_launch(void* const* d_in, const int* in_sizes, int n_in,
                              void* d_out, int out_size)
{
    const float* x = (const float*)d_in[0];
    const float* u = (const float*)d_in[1];
    const float* A = (const float*)d_in[2];
    const float* B = (const float*)d_in[3];
    const float* C = (const float*)d_in[4];

    float* x_next = (float*)d_out;
    float* y      = (float*)d_out + (size_t)MDIM * NDIM;

    __half *Aq, *Aq2, *Bq, *Bq2, *Cq, *XU, *Xn;
    cudaGetSymbolAddress((void**)&Aq,  g_Aq);
    cudaGetSymbolAddress((void**)&Aq2, g_Aq2);
    cudaGetSymbolAddress((void**)&Bq,  g_Bq);
    cudaGetSymbolAddress((void**)&Bq2, g_Bq2);
    cudaGetSymbolAddress((void**)&Cq,  g_Cq);
    cudaGetSymbolAddress((void**)&XU,  g_XU);
    cudaGetSymbolAddress((void**)&Xn,  g_Xn);

    cudaFuncSetAttribute(mma_gemm<0>, cudaFuncAttributeMaxDynamicSharedMemorySize, SMEM_SZ);
    cudaFuncSetAttribute(mma_gemm<1>, cudaFuncAttributeMaxDynamicSharedMemorySize, SMEM_SZ);

    const int T = 256;
    // 0: all weight quantization in one launch
    {
        int total4 = (NA + NB + NC) / 4;
        quantW<<<(total4 + T - 1) / T, T>>>(A, B, C, Aq, Aq2, Bq, Bq2, Cq);
    }
    // 1-2: activation splits
    splitk<<<(int)(((size_t)MDIM * NDIM / 4 + T - 1) / T), T>>>(x, NDIM, XU);
    splitk<<<(int)(((size_t)MDIM * MMID / 4 + T - 1) / T), T>>>(u, MMID, XU + 2 * NDIM);

    // 3: fused GEMM1: x_next = q8(XU @ [Aq | Aq/64 | Bq | Bq/64]^T), K=6144
    {
        dim3 grid(NDIM / TILEN, MDIM / TILEM);   // (32, 32)
        mma_gemm<0><<<grid, 256, SMEM_SZ>>>(
            XU, KEFF, KEFF / BKE,
            Aq, Aq2, Bq, Bq2,
            x_next, Xn, NDIM);
    }
    // 4: GEMM2: y = q8(Xn @ Cq^T), K=2048
    {
        dim3 grid(MMID / TILEN, MDIM / TILEM);   // (16, 32)
        mma_gemm<1><<<grid, 256, SMEM_SZ>>>(
            Xn, NDIM, NDIM / BKE,
            Cq, (const __half*)nullptr, (const __half*)nullptr, (const __half*)nullptr,
            y, (__half*)nullptr, MMID);
    }
}

// round 12
// speedup vs baseline: 1.5369x; 1.1549x over previous
#include <cuda_runtime.h>
#include <cuda_fp16.h>
#include <math.h>
#include <stdint.h>

// ============================================================================
// QuantizedSSM via mma.sync (HMMA) with chunked fp32 re-accumulation.
// HMMA internal accumulation rounds toward zero -> flush into a master fp32
// accumulator (RN) every 4 chunks (256 k-elements).
//   x_next = q8( x @ Aq^T + u @ Bq^T ) : fused fp16 GEMM, K = 6144
//   y      = q8( x_next @ Cq^T )       : exact fp16 GEMM, K = 2048
// R12 = R11 with A loads reverted to cp.async.cg (R11's .ca saturated L1 at
//       87% and starved the tensor pipe). Keeps wait_group 1 + cross-chunk
//       fragment prefetch (the convoy fix).
// ============================================================================

#define MDIM 4096
#define NDIM 2048
#define MMID 1024
#define KEFF (2*NDIM + 2*MMID)   // 6144

__device__ __half g_Aq [(size_t)NDIM * NDIM];
__device__ __half g_Aq2[(size_t)NDIM * NDIM];   // Aq / 64
__device__ __half g_Bq [(size_t)NDIM * MMID];
__device__ __half g_Bq2[(size_t)NDIM * MMID];   // Bq / 64
__device__ __half g_Cq [(size_t)MMID * NDIM];
__device__ __half g_XU [(size_t)MDIM * KEFF];   // [x1 | x2*64 | u1 | u2*64]
__device__ __half g_Xn [(size_t)MDIM * NDIM];   // x_next fp16 (exact)

// ----------------------------------------------------------------------------
// q8 = to_float8(v, 4, 3), branch-free bit version (exact vs reference).
// ----------------------------------------------------------------------------
__device__ __forceinline__ float q8(float v) {
    float a  = fabsf(v);
    float ae = a + 1e-8f;
    int e = ((__float_as_int(ae) >> 23) & 0xFF) - 127;
    e = min(max(e, -7), 7);
    float p  = __int_as_float((e + 127) << 23);   // 2^e
    float rp = __int_as_float((127 - e) << 23);   // 2^-e (exact)
    float m  = fmaf(a, rp, -1.0f);
    float mq = rintf(m * 8.0f);                   // round-half-even == jnp.round
    float r  = fmaf(mq, 0.125f, 1.0f) * p;
    return (v > 0.0f) ? r : ((v < 0.0f) ? -r : 0.0f);
}

// ----------------------------------------------------------------------------
// PTX helpers — all plain-target (sm_80+) instructions
// ----------------------------------------------------------------------------
__device__ __forceinline__ uint32_t smem_u32(const void* p) {
    uint32_t a;
    asm("{ .reg .u64 t; cvta.to.shared.u64 t, %1; cvt.u32.u64 %0, t; }"
        : "=r"(a) : "l"(p));
    return a;
}
__device__ __forceinline__ void cp16(uint32_t dst, const void* src) {
    asm volatile("cp.async.cg.shared.global [%0], [%1], 16;"
                 :: "r"(dst), "l"(src) : "memory");
}
__device__ __forceinline__ void cp_commit() {
    asm volatile("cp.async.commit_group;" ::: "memory");
}
__device__ __forceinline__ void ldsm4(uint32_t& r0, uint32_t& r1, uint32_t& r2,
                                      uint32_t& r3, uint32_t addr) {
    asm volatile("ldmatrix.sync.aligned.m8n8.x4.shared.b16 {%0,%1,%2,%3}, [%4];"
                 : "=r"(r0), "=r"(r1), "=r"(r2), "=r"(r3) : "r"(addr));
}
__device__ __forceinline__ void mma16816(float* d, const uint32_t* a, const uint32_t* b) {
    asm volatile(
        "mma.sync.aligned.m16n8k16.row.col.f32.f16.f16.f32 "
        "{%0,%1,%2,%3}, {%4,%5,%6,%7}, {%8,%9}, {%0,%1,%2,%3};"
        : "+f"(d[0]), "+f"(d[1]), "+f"(d[2]), "+f"(d[3])
        : "r"(a[0]), "r"(a[1]), "r"(a[2]), "r"(a[3]), "r"(b[0]), "r"(b[1]));
}

// SW128 swizzle (Swizzle<3,4,3>) on byte offsets within a 128B-row tile
__device__ __forceinline__ uint32_t swz(uint32_t o) { return o ^ ((o >> 3) & 0x70); }

// ----------------------------------------------------------------------------
// Prep kernels
// ----------------------------------------------------------------------------
#define NA (NDIM*NDIM)
#define NB (NDIM*MMID)
#define NC (MMID*NDIM)
__global__ void quantW(const float* __restrict__ A, const float* __restrict__ B,
                       const float* __restrict__ C,
                       __half* __restrict__ Aq, __half* __restrict__ Aq2,
                       __half* __restrict__ Bq, __half* __restrict__ Bq2,
                       __half* __restrict__ Cq)
{
    size_t i = ((size_t)blockIdx.x * blockDim.x + threadIdx.x) * 4;
    const float* in; __half *o1, *o2;
    if (i < NA)                { in = A + i;            o1 = Aq + i;  o2 = Aq2 + i; }
    else if (i < NA + NB)      { i -= NA; in = B + i;   o1 = Bq + i;  o2 = Bq2 + i; }
    else if (i < NA + NB + NC) { i -= NA + NB; in = C + i; o1 = Cq + i; o2 = nullptr; }
    else return;

    float4 v = *reinterpret_cast<const float4*>(in);
    float q0 = q8(v.x), q1 = q8(v.y), q2 = q8(v.z), q3 = q8(v.w);
    __half2 p0 = __floats2half2_rn(q0, q1);
    __half2 p1 = __floats2half2_rn(q2, q3);
    uint2 pk;
    pk.x = *reinterpret_cast<uint32_t*>(&p0);
    pk.y = *reinterpret_cast<uint32_t*>(&p1);
    *reinterpret_cast<uint2*>(o1) = pk;
    if (o2) {
        const float s = 0.015625f;  // 1/64, exact scaling
        __half2 s0 = __floats2half2_rn(q0 * s, q1 * s);
        __half2 s1 = __floats2half2_rn(q2 * s, q3 * s);
        uint2 sk;
        sk.x = *reinterpret_cast<uint32_t*>(&s0);
        sk.y = *reinterpret_cast<uint32_t*>(&s1);
        *reinterpret_cast<uint2*>(o2) = sk;
    }
}

// split fp32 -> plane1 = fp16(v) at [col], plane2 = fp16((v-plane1)*64) at [col+cols]
__global__ void splitk(const float* __restrict__ src, int cols, __half* __restrict__ dst) {
    size_t idx = (size_t)blockIdx.x * blockDim.x + threadIdx.x;
    size_t i4 = idx * 4;
    if (i4 >= (size_t)MDIM * cols) return;
    int row = (int)(i4 / cols);
    int col = (int)(i4 % cols);
    float4 v = *reinterpret_cast<const float4*>(src + i4);
    float f[4] = {v.x, v.y, v.z, v.w};
    __half h1[4], h2[4];
#pragma unroll
    for (int j = 0; j < 4; j++) {
        __half b1 = __float2half_rn(f[j]);
        float r1 = f[j] - __half2float(b1);   // exact in fp32
        h1[j] = b1;
        h2[j] = __float2half_rn(r1 * 64.0f);  // scaled into normal fp16 range
    }
    __half* d0 = dst + (size_t)row * KEFF + col;
    auto pack = [](__half* h) {
        __half2 p0(h[0], h[1]), p1(h[2], h[3]);
        uint2 r;
        r.x = *reinterpret_cast<uint32_t*>(&p0);
        r.y = *reinterpret_cast<uint32_t*>(&p1);
        return r;
    };
    *reinterpret_cast<uint2*>(d0)        = pack(h1);
    *reinterpret_cast<uint2*>(d0 + cols) = pack(h2);
}

// ----------------------------------------------------------------------------
// HMMA GEMM-NT, 128x64 CTA tile, BK=64, 4-stage single-chunk pipeline,
// double-buffered ldmatrix fragments WITH cross-chunk ks0 prefetch.
// 8 warps: wm = wid&3 (4 x 32 rows), wn = wid>>2 (2 x 32 cols).
// MODE 0 (fused GEMM1): chunk c -> B segment
//   c in [ 0,32): Aq   col (c&31)*64, ld NDIM   (pairs x plane1)
//   c in [32,64): Aq2  col (c&31)*64, ld NDIM   (pairs x plane2)
//   c in [64,80): Bq   col (c&15)*64, ld MMID   (pairs u plane1)
//   c in [80,96): Bq2  col (c&15)*64, ld MMID   (pairs u plane2)
//   epilogue: q8 -> fp32 outp + fp16 aux
// MODE 1 (GEMM2): B = P0 col (c&31)*64, ld NDIM; epilogue q8 -> fp32 outp.
// nchunk must be a multiple of 4 (96 and 32 are).
// ----------------------------------------------------------------------------
#define NSTAGE 4
#define BKE 64
#define TILEM 128
#define TILEN 64
#define A_BYTES (TILEM * 128)                   // 16 KB
#define B_BYTES (TILEN * 128)                   //  8 KB
#define STAGE_BYTES (A_BYTES + B_BYTES)         // 24 KB
#define SMEM_SZ (NSTAGE * STAGE_BYTES)          // 96 KB

template <int MODE>
__global__ void __launch_bounds__(256, 2)
mma_gemm(const __half* __restrict__ Aop, int ldA, int nchunk,
         const __half* __restrict__ P0, const __half* __restrict__ P1,
         const __half* __restrict__ P2, const __half* __restrict__ P3,
         float* __restrict__ outp, __half* __restrict__ aux, int ldOut)
{
    extern __shared__ char smem[];
    const uint32_t sb = smem_u32(smem);
    const int tid  = threadIdx.x;
    const int lane = tid & 31;
    const int wid  = tid >> 5;
    const int wm   = wid & 3;    // 4 m-slices of 32
    const int wn   = wid >> 2;   // 2 n-slices of 32
    const int m0 = blockIdx.y * TILEM;
    const int n0 = blockIdx.x * TILEN;

    // A: 128 rows, 2 threads/row, 4 x 16B each.  B: 64 rows, 4 threads/row, 2 x 16B.
    const int alr  = tid >> 1;
    const int alc0 = (tid & 1) * 4;
    const int blr  = tid >> 2;
    const int blc0 = (tid & 3) * 2;

    auto load_chunk = [&](int c) {
        const uint32_t sA = sb + (c % NSTAGE) * STAGE_BYTES;
        const uint32_t sB = sA + A_BYTES;
        const __half* arow = Aop + (size_t)(m0 + alr) * ldA + c * BKE;
        const __half* bsrc; int ldB;
        if (MODE == 0) {
            if (c < 64) { bsrc = ((c < 32) ? P0 : P1) + (size_t)(c & 31) * BKE; ldB = NDIM; }
            else        { bsrc = ((c < 80) ? P2 : P3) + (size_t)(c & 15) * BKE; ldB = MMID; }
        } else {
            bsrc = P0 + (size_t)(c & 31) * BKE; ldB = NDIM;
        }
        const __half* brow = bsrc + (size_t)(n0 + blr) * ldB;
#pragma unroll
        for (int j = 0; j < 4; j++) {
            int c16 = alc0 + j;
            cp16(sA + swz(alr * 128 + c16 * 16), arow + c16 * 8);
        }
#pragma unroll
        for (int j = 0; j < 2; j++) {
            int c16 = blc0 + j;
            cp16(sB + swz(blr * 128 + c16 * 16), brow + c16 * 8);
        }
        cp_commit();
    };

    float mst[2][4][4];   // master fp32 accumulator (RN adds)
    float acc[2][4][4];   // HMMA chain accumulator (short chains only)
#pragma unroll
    for (int i = 0; i < 2; i++)
#pragma unroll
        for (int j = 0; j < 4; j++)
#pragma unroll
            for (int k = 0; k < 4; k++) mst[i][j][k] = 0.0f;

    // fragment double buffers
    uint32_t af[2][2][4];   // [buf][mt][reg]
    uint32_t bf[2][2][4];   // [buf][np][reg]

    // per-thread ldsm base rows
    const int arow_lo = wm * 32 + ((lane >> 3) & 1) * 8 + (lane & 7);  // + mt*16
    const int aku_off = (lane >> 4);                                    // + ks*2
    const int brow_lo = wn * 32 + (lane >> 4) * 8 + (lane & 7);         // + np*16
    const int bku_off = ((lane >> 3) & 1);                              // + ks*2

    auto load_frags = [&](uint32_t sA, uint32_t sB, int ks, int buf) {
#pragma unroll
        for (int mt = 0; mt < 2; mt++) {
            int row = arow_lo + mt * 16;
            int ku  = ks * 2 + aku_off;
            ldsm4(af[buf][mt][0], af[buf][mt][1], af[buf][mt][2], af[buf][mt][3],
                  sA + swz(row * 128 + ku * 16));
        }
#pragma unroll
        for (int np = 0; np < 2; np++) {
            int row = brow_lo + np * 16;
            int ku  = ks * 2 + bku_off;
            ldsm4(bf[buf][np][0], bf[buf][np][1], bf[buf][np][2], bf[buf][np][3],
                  sB + swz(row * 128 + ku * 16));
        }
    };

    // prologue
    load_chunk(0);
    load_chunk(1);
    load_chunk(2);
    asm volatile("cp.async.wait_group 1;" ::: "memory");   // chunks 0,1 resident
    __syncthreads();
    {   // preload (chunk 0, ks0) into buf 0
        const uint32_t sA0 = sb + 0 * STAGE_BYTES;
        load_frags(sA0, sA0 + A_BYTES, 0, 0);
    }

    for (int c = 0; c < nchunk; c++) {
        const int s = c % NSTAGE;

        if (c > 0) {
            // chunks c and c+1 resident & (after barrier) CTA-visible
            asm volatile("cp.async.wait_group 1;" ::: "memory");
            __syncthreads();
        }

        if (c + 3 < nchunk) load_chunk(c + 3);
        else                cp_commit();        // keep group accounting uniform

        const uint32_t sA = sb + s * STAGE_BYTES;
        const uint32_t sB = sA + A_BYTES;

        if ((c & 3) == 0) {                      // start fresh HMMA chain
#pragma unroll
            for (int i = 0; i < 2; i++)
#pragma unroll
                for (int j = 0; j < 4; j++)
#pragma unroll
                    for (int k = 0; k < 4; k++) acc[i][j][k] = 0.0f;
        }

        // buf (0) holds (c, ks0) on loop entry; MMAs issue immediately.
        // ks<3: prefetch (c, ks+1); ks==3: prefetch (c+1, ks0) — its stage is
        // resident (wait_group 1) and distinct from the stage load_chunk is
        // writing ((c+3)%4 == (c-1)%4 != (c+1)%4).
#pragma unroll
        for (int ks = 0; ks < 4; ks++) {
            const int cur = ks & 1, nxt = cur ^ 1;
            if (ks < 3) {
                load_frags(sA, sB, ks + 1, nxt);
            } else if (c + 1 < nchunk) {
                const uint32_t sA1 = sb + ((c + 1) % NSTAGE) * STAGE_BYTES;
                load_frags(sA1, sA1 + A_BYTES, 0, nxt);
            }
#pragma unroll
            for (int mt = 0; mt < 2; mt++)
#pragma unroll
                for (int nt = 0; nt < 4; nt++)
                    mma16816(acc[mt][nt], af[cur][mt], &bf[cur][nt >> 1][(nt & 1) * 2]);
        }

        if ((c & 3) == 3) {                      // flush chain into master (RN)
#pragma unroll
            for (int i = 0; i < 2; i++)
#pragma unroll
                for (int j = 0; j < 4; j++)
#pragma unroll
                    for (int k = 0; k < 4; k++) mst[i][j][k] += acc[i][j][k];
        }
    }

    // Epilogue: q8 then direct stores
#pragma unroll
    for (int mt = 0; mt < 2; mt++) {
#pragma unroll
        for (int nt = 0; nt < 4; nt++) {
            int row0 = m0 + wm * 32 + mt * 16 + (lane >> 2);
            int col  = n0 + wn * 32 + nt * 8 + 2 * (lane & 3);
#pragma unroll
            for (int h = 0; h < 2; h++) {
                int row = row0 + h * 8;
                float v0 = q8(mst[mt][nt][h * 2 + 0]);
                float v1 = q8(mst[mt][nt][h * 2 + 1]);
                size_t g = (size_t)row * ldOut + col;
                *reinterpret_cast<float2*>(outp + g) = make_float2(v0, v1);
                if (MODE == 0) {
                    __half2 hv = __floats2half2_rn(v0, v1);
                    *reinterpret_cast<__half2*>(aux + g) = hv;
                }
            }
        }
    }
}

// ----------------------------------------------------------------------------
// Host launcher
// Launch order (ncu -s capture at index 3 = mma_gemm<0>):
//   0: quantW   1: splitk(x)   2: splitk(u)   3: gemm1   4: gemm2
// ----------------------------------------------------------------------------
extern "C" void kernel_launch(void* const* d_in, const int* in_sizes, int n_in,
                              void* d_out, int out_size)
{
    const float* x = (const float*)d_in[0];
    const float* u = (const float*)d_in[1];
    const float* A = (const float*)d_in[2];
    const float* B = (const float*)d_in[3];
    const float* C = (const float*)d_in[4];

    float* x_next = (float*)d_out;
    float* y      = (float*)d_out + (size_t)MDIM * NDIM;

    __half *Aq, *Aq2, *Bq, *Bq2, *Cq, *XU, *Xn;
    cudaGetSymbolAddress((void**)&Aq,  g_Aq);
    cudaGetSymbolAddress((void**)&Aq2, g_Aq2);
    cudaGetSymbolAddress((void**)&Bq,  g_Bq);
    cudaGetSymbolAddress((void**)&Bq2, g_Bq2);
    cudaGetSymbolAddress((void**)&Cq,  g_Cq);
    cudaGetSymbolAddress((void**)&XU,  g_XU);
    cudaGetSymbolAddress((void**)&Xn,  g_Xn);

    cudaFuncSetAttribute(mma_gemm<0>, cudaFuncAttributeMaxDynamicSharedMemorySize, SMEM_SZ);
    cudaFuncSetAttribute(mma_gemm<1>, cudaFuncAttributeMaxDynamicSharedMemorySize, SMEM_SZ);

    const int T = 256;
    // 0: all weight quantization in one launch
    {
        int total4 = (NA + NB + NC) / 4;
        quantW<<<(total4 + T - 1) / T, T>>>(A, B, C, Aq, Aq2, Bq, Bq2, Cq);
    }
    // 1-2: activation splits
    splitk<<<(int)(((size_t)MDIM * NDIM / 4 + T - 1) / T), T>>>(x, NDIM, XU);
    splitk<<<(int)(((size_t)MDIM * MMID / 4 + T - 1) / T), T>>>(u, MMID, XU + 2 * NDIM);

    // 3: fused GEMM1: x_next = q8(XU @ [Aq | Aq/64 | Bq | Bq/64]^T), K=6144
    {
        dim3 grid(NDIM / TILEN, MDIM / TILEM);   // (32, 32)
        mma_gemm<0><<<grid, 256, SMEM_SZ>>>(
            XU, KEFF, KEFF / BKE,
            Aq, Aq2, Bq, Bq2,
            x_next, Xn, NDIM);
    }
    // 4: GEMM2: y = q8(Xn @ Cq^T), K=2048
    {
        dim3 grid(MMID / TILEN, MDIM / TILEM);   // (16, 32)
        mma_gemm<1><<<grid, 256, SMEM_SZ>>>(
            Xn, NDIM, NDIM / BKE,
            Cq, (const __half*)nullptr, (const __half*)nullptr, (const __half*)nullptr,
            y, (__half*)nullptr, MMID);
    }
}

// round 13
// speedup vs baseline: 1.5903x; 1.0348x over previous
#include <cuda_runtime.h>
#include <cuda_fp16.h>
#include <math.h>
#include <stdint.h>

// ============================================================================
// QuantizedSSM via mma.sync (HMMA) with chunked fp32 re-accumulation.
// HMMA internal accumulation rounds toward zero -> flush into a master fp32
// accumulator (RN) every CHAIN chunks.
//   x_next = q8( x @ Aq^T + u @ Bq^T ) : fused fp16 GEMM, K = 6144
//   y      = q8( x_next @ Cq^T )       : exact fp16 GEMM, K = 2048
// R13 (base = R12): chain length 4 -> 8 (flush tax halved; RZ bias ~8e-5 abs,
//     below fp32 ordering noise) + statically unrolled 8-chunk inner loop so
//     zeroing/flush schedule across chunk boundaries.
// ============================================================================

#define MDIM 4096
#define NDIM 2048
#define MMID 1024
#define KEFF (2*NDIM + 2*MMID)   // 6144

__device__ __half g_Aq [(size_t)NDIM * NDIM];
__device__ __half g_Aq2[(size_t)NDIM * NDIM];   // Aq / 64
__device__ __half g_Bq [(size_t)NDIM * MMID];
__device__ __half g_Bq2[(size_t)NDIM * MMID];   // Bq / 64
__device__ __half g_Cq [(size_t)MMID * NDIM];
__device__ __half g_XU [(size_t)MDIM * KEFF];   // [x1 | x2*64 | u1 | u2*64]
__device__ __half g_Xn [(size_t)MDIM * NDIM];   // x_next fp16 (exact)

// ----------------------------------------------------------------------------
// q8 = to_float8(v, 4, 3), branch-free bit version (exact vs reference).
// ----------------------------------------------------------------------------
__device__ __forceinline__ float q8(float v) {
    float a  = fabsf(v);
    float ae = a + 1e-8f;
    int e = ((__float_as_int(ae) >> 23) & 0xFF) - 127;
    e = min(max(e, -7), 7);
    float p  = __int_as_float((e + 127) << 23);   // 2^e
    float rp = __int_as_float((127 - e) << 23);   // 2^-e (exact)
    float m  = fmaf(a, rp, -1.0f);
    float mq = rintf(m * 8.0f);                   // round-half-even == jnp.round
    float r  = fmaf(mq, 0.125f, 1.0f) * p;
    return (v > 0.0f) ? r : ((v < 0.0f) ? -r : 0.0f);
}

// ----------------------------------------------------------------------------
// PTX helpers — all plain-target (sm_80+) instructions
// ----------------------------------------------------------------------------
__device__ __forceinline__ uint32_t smem_u32(const void* p) {
    uint32_t a;
    asm("{ .reg .u64 t; cvta.to.shared.u64 t, %1; cvt.u32.u64 %0, t; }"
        : "=r"(a) : "l"(p));
    return a;
}
__device__ __forceinline__ void cp16(uint32_t dst, const void* src) {
    asm volatile("cp.async.cg.shared.global [%0], [%1], 16;"
                 :: "r"(dst), "l"(src) : "memory");
}
__device__ __forceinline__ void cp_commit() {
    asm volatile("cp.async.commit_group;" ::: "memory");
}
__device__ __forceinline__ void ldsm4(uint32_t& r0, uint32_t& r1, uint32_t& r2,
                                      uint32_t& r3, uint32_t addr) {
    asm volatile("ldmatrix.sync.aligned.m8n8.x4.shared.b16 {%0,%1,%2,%3}, [%4];"
                 : "=r"(r0), "=r"(r1), "=r"(r2), "=r"(r3) : "r"(addr));
}
__device__ __forceinline__ void mma16816(float* d, const uint32_t* a, const uint32_t* b) {
    asm volatile(
        "mma.sync.aligned.m16n8k16.row.col.f32.f16.f16.f32 "
        "{%0,%1,%2,%3}, {%4,%5,%6,%7}, {%8,%9}, {%0,%1,%2,%3};"
        : "+f"(d[0]), "+f"(d[1]), "+f"(d[2]), "+f"(d[3])
        : "r"(a[0]), "r"(a[1]), "r"(a[2]), "r"(a[3]), "r"(b[0]), "r"(b[1]));
}

// SW128 swizzle (Swizzle<3,4,3>) on byte offsets within a 128B-row tile
__device__ __forceinline__ uint32_t swz(uint32_t o) { return o ^ ((o >> 3) & 0x70); }

// ----------------------------------------------------------------------------
// Prep kernels
// ----------------------------------------------------------------------------
#define NA (NDIM*NDIM)
#define NB (NDIM*MMID)
#define NC (MMID*NDIM)
__global__ void quantW(const float* __restrict__ A, const float* __restrict__ B,
                       const float* __restrict__ C,
                       __half* __restrict__ Aq, __half* __restrict__ Aq2,
                       __half* __restrict__ Bq, __half* __restrict__ Bq2,
                       __half* __restrict__ Cq)
{
    size_t i = ((size_t)blockIdx.x * blockDim.x + threadIdx.x) * 4;
    const float* in; __half *o1, *o2;
    if (i < NA)                { in = A + i;            o1 = Aq + i;  o2 = Aq2 + i; }
    else if (i < NA + NB)      { i -= NA; in = B + i;   o1 = Bq + i;  o2 = Bq2 + i; }
    else if (i < NA + NB + NC) { i -= NA + NB; in = C + i; o1 = Cq + i; o2 = nullptr; }
    else return;

    float4 v = *reinterpret_cast<const float4*>(in);
    float q0 = q8(v.x), q1 = q8(v.y), q2 = q8(v.z), q3 = q8(v.w);
    __half2 p0 = __floats2half2_rn(q0, q1);
    __half2 p1 = __floats2half2_rn(q2, q3);
    uint2 pk;
    pk.x = *reinterpret_cast<uint32_t*>(&p0);
    pk.y = *reinterpret_cast<uint32_t*>(&p1);
    *reinterpret_cast<uint2*>(o1) = pk;
    if (o2) {
        const float s = 0.015625f;  // 1/64, exact scaling
        __half2 s0 = __floats2half2_rn(q0 * s, q1 * s);
        __half2 s1 = __floats2half2_rn(q2 * s, q3 * s);
        uint2 sk;
        sk.x = *reinterpret_cast<uint32_t*>(&s0);
        sk.y = *reinterpret_cast<uint32_t*>(&s1);
        *reinterpret_cast<uint2*>(o2) = sk;
    }
}

// split fp32 -> plane1 = fp16(v) at [col], plane2 = fp16((v-plane1)*64) at [col+cols]
__global__ void splitk(const float* __restrict__ src, int cols, __half* __restrict__ dst) {
    size_t idx = (size_t)blockIdx.x * blockDim.x + threadIdx.x;
    size_t i4 = idx * 4;
    if (i4 >= (size_t)MDIM * cols) return;
    int row = (int)(i4 / cols);
    int col = (int)(i4 % cols);
    float4 v = *reinterpret_cast<const float4*>(src + i4);
    float f[4] = {v.x, v.y, v.z, v.w};
    __half h1[4], h2[4];
#pragma unroll
    for (int j = 0; j < 4; j++) {
        __half b1 = __float2half_rn(f[j]);
        float r1 = f[j] - __half2float(b1);   // exact in fp32
        h1[j] = b1;
        h2[j] = __float2half_rn(r1 * 64.0f);  // scaled into normal fp16 range
    }
    __half* d0 = dst + (size_t)row * KEFF + col;
    auto pack = [](__half* h) {
        __half2 p0(h[0], h[1]), p1(h[2], h[3]);
        uint2 r;
        r.x = *reinterpret_cast<uint32_t*>(&p0);
        r.y = *reinterpret_cast<uint32_t*>(&p1);
        return r;
    };
    *reinterpret_cast<uint2*>(d0)        = pack(h1);
    *reinterpret_cast<uint2*>(d0 + cols) = pack(h2);
}

// ----------------------------------------------------------------------------
// HMMA GEMM-NT, 128x64 CTA tile, BK=64, 4-stage single-chunk pipeline,
// double-buffered ldmatrix fragments WITH cross-chunk ks0 prefetch,
// 8-chunk HMMA chains flushed to fp32 master, statically unrolled.
// 8 warps: wm = wid&3 (4 x 32 rows), wn = wid>>2 (2 x 32 cols).
// MODE 0 (fused GEMM1): chunk c -> B segment
//   c in [ 0,32): Aq   col (c&31)*64, ld NDIM   (pairs x plane1)
//   c in [32,64): Aq2  col (c&31)*64, ld NDIM   (pairs x plane2)
//   c in [64,80): Bq   col (c&15)*64, ld MMID   (pairs u plane1)
//   c in [80,96): Bq2  col (c&15)*64, ld MMID   (pairs u plane2)
//   epilogue: q8 -> fp32 outp + fp16 aux
// MODE 1 (GEMM2): B = P0 col (c&31)*64, ld NDIM; epilogue q8 -> fp32 outp.
// nchunk must be a multiple of 8 (96 and 32 are).
// ----------------------------------------------------------------------------
#define NSTAGE 4
#define BKE 64
#define TILEM 128
#define TILEN 64
#define CHAIN 8
#define A_BYTES (TILEM * 128)                   // 16 KB
#define B_BYTES (TILEN * 128)                   //  8 KB
#define STAGE_BYTES (A_BYTES + B_BYTES)         // 24 KB
#define SMEM_SZ (NSTAGE * STAGE_BYTES)          // 96 KB

template <int MODE>
__global__ void __launch_bounds__(256, 2)
mma_gemm(const __half* __restrict__ Aop, int ldA, int nchunk,
         const __half* __restrict__ P0, const __half* __restrict__ P1,
         const __half* __restrict__ P2, const __half* __restrict__ P3,
         float* __restrict__ outp, __half* __restrict__ aux, int ldOut)
{
    extern __shared__ char smem[];
    const uint32_t sb = smem_u32(smem);
    const int tid  = threadIdx.x;
    const int lane = tid & 31;
    const int wid  = tid >> 5;
    const int wm   = wid & 3;    // 4 m-slices of 32
    const int wn   = wid >> 2;   // 2 n-slices of 32
    const int m0 = blockIdx.y * TILEM;
    const int n0 = blockIdx.x * TILEN;

    // A: 128 rows, 2 threads/row, 4 x 16B each.  B: 64 rows, 4 threads/row, 2 x 16B.
    const int alr  = tid >> 1;
    const int alc0 = (tid & 1) * 4;
    const int blr  = tid >> 2;
    const int blc0 = (tid & 3) * 2;

    auto load_chunk = [&](int c) {
        const uint32_t sA = sb + (c % NSTAGE) * STAGE_BYTES;
        const uint32_t sB = sA + A_BYTES;
        const __half* arow = Aop + (size_t)(m0 + alr) * ldA + c * BKE;
        const __half* bsrc; int ldB;
        if (MODE == 0) {
            if (c < 64) { bsrc = ((c < 32) ? P0 : P1) + (size_t)(c & 31) * BKE; ldB = NDIM; }
            else        { bsrc = ((c < 80) ? P2 : P3) + (size_t)(c & 15) * BKE; ldB = MMID; }
        } else {
            bsrc = P0 + (size_t)(c & 31) * BKE; ldB = NDIM;
        }
        const __half* brow = bsrc + (size_t)(n0 + blr) * ldB;
#pragma unroll
        for (int j = 0; j < 4; j++) {
            int c16 = alc0 + j;
            cp16(sA + swz(alr * 128 + c16 * 16), arow + c16 * 8);
        }
#pragma unroll
        for (int j = 0; j < 2; j++) {
            int c16 = blc0 + j;
            cp16(sB + swz(blr * 128 + c16 * 16), brow + c16 * 8);
        }
        cp_commit();
    };

    float mst[2][4][4];   // master fp32 accumulator (RN adds)
    float acc[2][4][4];   // HMMA chain accumulator (8-chunk chains)
#pragma unroll
    for (int i = 0; i < 2; i++)
#pragma unroll
        for (int j = 0; j < 4; j++)
#pragma unroll
            for (int k = 0; k < 4; k++) mst[i][j][k] = 0.0f;

    // fragment double buffers
    uint32_t af[2][2][4];   // [buf][mt][reg]
    uint32_t bf[2][2][4];   // [buf][np][reg]

    // per-thread ldsm base rows
    const int arow_lo = wm * 32 + ((lane >> 3) & 1) * 8 + (lane & 7);  // + mt*16
    const int aku_off = (lane >> 4);                                    // + ks*2
    const int brow_lo = wn * 32 + (lane >> 4) * 8 + (lane & 7);         // + np*16
    const int bku_off = ((lane >> 3) & 1);                              // + ks*2

    auto load_frags = [&](uint32_t sA, uint32_t sB, int ks, int buf) {
#pragma unroll
        for (int mt = 0; mt < 2; mt++) {
            int row = arow_lo + mt * 16;
            int ku  = ks * 2 + aku_off;
            ldsm4(af[buf][mt][0], af[buf][mt][1], af[buf][mt][2], af[buf][mt][3],
                  sA + swz(row * 128 + ku * 16));
        }
#pragma unroll
        for (int np = 0; np < 2; np++) {
            int row = brow_lo + np * 16;
            int ku  = ks * 2 + bku_off;
            ldsm4(bf[buf][np][0], bf[buf][np][1], bf[buf][np][2], bf[buf][np][3],
                  sB + swz(row * 128 + ku * 16));
        }
    };

    // prologue
    load_chunk(0);
    load_chunk(1);
    load_chunk(2);
    asm volatile("cp.async.wait_group 1;" ::: "memory");   // chunks 0,1 resident
    __syncthreads();
    {   // preload (chunk 0, ks0) into buf 0
        const uint32_t sA0 = sb + 0 * STAGE_BYTES;
        load_frags(sA0, sA0 + A_BYTES, 0, 0);
    }

    const int nouter = nchunk / CHAIN;
    for (int cb = 0; cb < nouter; cb++) {
        // start fresh HMMA chain (statically placed)
#pragma unroll
        for (int i = 0; i < 2; i++)
#pragma unroll
            for (int j = 0; j < 4; j++)
#pragma unroll
                for (int k = 0; k < 4; k++) acc[i][j][k] = 0.0f;

#pragma unroll
        for (int ci = 0; ci < CHAIN; ci++) {
            const int c = cb * CHAIN + ci;
            const int s = c % NSTAGE;

            if (cb > 0 || ci > 0) {
                // chunks c and c+1 resident & (after barrier) CTA-visible
                asm volatile("cp.async.wait_group 1;" ::: "memory");
                __syncthreads();
            }

            if (c + 3 < nchunk) load_chunk(c + 3);
            else                cp_commit();        // keep group accounting uniform

            const uint32_t sA = sb + s * STAGE_BYTES;
            const uint32_t sB = sA + A_BYTES;

            // buf (0) holds (c, ks0) on loop entry; MMAs issue immediately.
            // ks<3: prefetch (c, ks+1); ks==3: prefetch (c+1, ks0) — its stage
            // is resident (wait_group 1) and distinct from the stage being
            // written ((c+3)%4 == (c-1)%4 != (c+1)%4).
#pragma unroll
            for (int ks = 0; ks < 4; ks++) {
                const int cur = ks & 1, nxt = cur ^ 1;
                if (ks < 3) {
                    load_frags(sA, sB, ks + 1, nxt);
                } else if (c + 1 < nchunk) {
                    const uint32_t sA1 = sb + ((c + 1) % NSTAGE) * STAGE_BYTES;
                    load_frags(sA1, sA1 + A_BYTES, 0, nxt);
                }
#pragma unroll
                for (int mt = 0; mt < 2; mt++)
#pragma unroll
                    for (int nt = 0; nt < 4; nt++)
                        mma16816(acc[mt][nt], af[cur][mt], &bf[cur][nt >> 1][(nt & 1) * 2]);
            }
        }

        // flush chain into master (RN), statically placed
#pragma unroll
        for (int i = 0; i < 2; i++)
#pragma unroll
            for (int j = 0; j < 4; j++)
#pragma unroll
                for (int k = 0; k < 4; k++) mst[i][j][k] += acc[i][j][k];
    }

    // Epilogue: q8 then direct stores
#pragma unroll
    for (int mt = 0; mt < 2; mt++) {
#pragma unroll
        for (int nt = 0; nt < 4; nt++) {
            int row0 = m0 + wm * 32 + mt * 16 + (lane >> 2);
            int col  = n0 + wn * 32 + nt * 8 + 2 * (lane & 3);
#pragma unroll
            for (int h = 0; h < 2; h++) {
                int row = row0 + h * 8;
                float v0 = q8(mst[mt][nt][h * 2 + 0]);
                float v1 = q8(mst[mt][nt][h * 2 + 1]);
                size_t g = (size_t)row * ldOut + col;
                *reinterpret_cast<float2*>(outp + g) = make_float2(v0, v1);
                if (MODE == 0) {
                    __half2 hv = __floats2half2_rn(v0, v1);
                    *reinterpret_cast<__half2*>(aux + g) = hv;
                }
            }
        }
    }
}

// ----------------------------------------------------------------------------
// Host launcher
// Launch order (ncu capture lands on index 3 = mma_gemm<0>):
//   0: quantW   1: splitk(x)   2: splitk(u)   3: gemm1   4: gemm2
// ----------------------------------------------------------------------------
extern "C" void kernel_launch(void* const* d_in, const int* in_sizes, int n_in,
                              void* d_out, int out_size)
{
    const float* x = (const float*)d_in[0];
    const float* u = (const float*)d_in[1];
    const float* A = (const float*)d_in[2];
    const float* B = (const float*)d_in[3];
    const float* C = (const float*)d_in[4];

    float* x_next = (float*)d_out;
    float* y      = (float*)d_out + (size_t)MDIM * NDIM;

    __half *Aq, *Aq2, *Bq, *Bq2, *Cq, *XU, *Xn;
    cudaGetSymbolAddress((void**)&Aq,  g_Aq);
    cudaGetSymbolAddress((void**)&Aq2, g_Aq2);
    cudaGetSymbolAddress((void**)&Bq,  g_Bq);
    cudaGetSymbolAddress((void**)&Bq2, g_Bq2);
    cudaGetSymbolAddress((void**)&Cq,  g_Cq);
    cudaGetSymbolAddress((void**)&XU,  g_XU);
    cudaGetSymbolAddress((void**)&Xn,  g_Xn);

    cudaFuncSetAttribute(mma_gemm<0>, cudaFuncAttributeMaxDynamicSharedMemorySize, SMEM_SZ);
    cudaFuncSetAttribute(mma_gemm<1>, cudaFuncAttributeMaxDynamicSharedMemorySize, SMEM_SZ);

    const int T = 256;
    // 0: all weight quantization in one launch
    {
        int total4 = (NA + NB + NC) / 4;
        quantW<<<(total4 + T - 1) / T, T>>>(A, B, C, Aq, Aq2, Bq, Bq2, Cq);
    }
    // 1-2: activation splits
    splitk<<<(int)(((size_t)MDIM * NDIM / 4 + T - 1) / T), T>>>(x, NDIM, XU);
    splitk<<<(int)(((size_t)MDIM * MMID / 4 + T - 1) / T), T>>>(u, MMID, XU + 2 * NDIM);

    // 3: fused GEMM1: x_next = q8(XU @ [Aq | Aq/64 | Bq | Bq/64]^T), K=6144
    {
        dim3 grid(NDIM / TILEN, MDIM / TILEM);   // (32, 32)
        mma_gemm<0><<<grid, 256, SMEM_SZ>>>(
            XU, KEFF, KEFF / BKE,
            Aq, Aq2, Bq, Bq2,
            x_next, Xn, NDIM);
    }
    // 4: GEMM2: y = q8(Xn @ Cq^T), K=2048
    {
        dim3 grid(MMID / TILEN, MDIM / TILEM);   // (16, 32)
        mma_gemm<1><<<grid, 256, SMEM_SZ>>>(
            Xn, NDIM, NDIM / BKE,
            Cq, (const __half*)nullptr, (const __half*)nullptr, (const __half*)nullptr,
            y, (__half*)nullptr, MMID);
    }
}

// round 14
// speedup vs baseline: 1.5970x; 1.0042x over previous
#include <cuda_runtime.h>
#include <cuda_fp16.h>
#include <math.h>
#include <stdint.h>

// ============================================================================
// QuantizedSSM via mma.sync (HMMA) with chunked fp32 re-accumulation.
// HMMA internal accumulation rounds toward zero -> flush into a master fp32
// accumulator (RN) every CHAIN chunks.
//   x_next = q8( x @ Aq^T + u @ Bq^T ) : fused fp16 GEMM, K = 6144
//   y      = q8( x_next @ Cq^T )       : exact fp16 GEMM, K = 2048
// R14 (base = R13): chain length 8 -> 16 (flush tax halved again; calibrated
//     RZ-bias increment ~+2e-5, rel_err stays ~3.3e-4 << 1e-3).
// ============================================================================

#define MDIM 4096
#define NDIM 2048
#define MMID 1024
#define KEFF (2*NDIM + 2*MMID)   // 6144

__device__ __half g_Aq [(size_t)NDIM * NDIM];
__device__ __half g_Aq2[(size_t)NDIM * NDIM];   // Aq / 64
__device__ __half g_Bq [(size_t)NDIM * MMID];
__device__ __half g_Bq2[(size_t)NDIM * MMID];   // Bq / 64
__device__ __half g_Cq [(size_t)MMID * NDIM];
__device__ __half g_XU [(size_t)MDIM * KEFF];   // [x1 | x2*64 | u1 | u2*64]
__device__ __half g_Xn [(size_t)MDIM * NDIM];   // x_next fp16 (exact)

// ----------------------------------------------------------------------------
// q8 = to_float8(v, 4, 3), branch-free bit version (exact vs reference).
// ----------------------------------------------------------------------------
__device__ __forceinline__ float q8(float v) {
    float a  = fabsf(v);
    float ae = a + 1e-8f;
    int e = ((__float_as_int(ae) >> 23) & 0xFF) - 127;
    e = min(max(e, -7), 7);
    float p  = __int_as_float((e + 127) << 23);   // 2^e
    float rp = __int_as_float((127 - e) << 23);   // 2^-e (exact)
    float m  = fmaf(a, rp, -1.0f);
    float mq = rintf(m * 8.0f);                   // round-half-even == jnp.round
    float r  = fmaf(mq, 0.125f, 1.0f) * p;
    return (v > 0.0f) ? r : ((v < 0.0f) ? -r : 0.0f);
}

// ----------------------------------------------------------------------------
// PTX helpers — all plain-target (sm_80+) instructions
// ----------------------------------------------------------------------------
__device__ __forceinline__ uint32_t smem_u32(const void* p) {
    uint32_t a;
    asm("{ .reg .u64 t; cvta.to.shared.u64 t, %1; cvt.u32.u64 %0, t; }"
        : "=r"(a) : "l"(p));
    return a;
}
__device__ __forceinline__ void cp16(uint32_t dst, const void* src) {
    asm volatile("cp.async.cg.shared.global [%0], [%1], 16;"
                 :: "r"(dst), "l"(src) : "memory");
}
__device__ __forceinline__ void cp_commit() {
    asm volatile("cp.async.commit_group;" ::: "memory");
}
__device__ __forceinline__ void ldsm4(uint32_t& r0, uint32_t& r1, uint32_t& r2,
                                      uint32_t& r3, uint32_t addr) {
    asm volatile("ldmatrix.sync.aligned.m8n8.x4.shared.b16 {%0,%1,%2,%3}, [%4];"
                 : "=r"(r0), "=r"(r1), "=r"(r2), "=r"(r3) : "r"(addr));
}
__device__ __forceinline__ void mma16816(float* d, const uint32_t* a, const uint32_t* b) {
    asm volatile(
        "mma.sync.aligned.m16n8k16.row.col.f32.f16.f16.f32 "
        "{%0,%1,%2,%3}, {%4,%5,%6,%7}, {%8,%9}, {%0,%1,%2,%3};"
        : "+f"(d[0]), "+f"(d[1]), "+f"(d[2]), "+f"(d[3])
        : "r"(a[0]), "r"(a[1]), "r"(a[2]), "r"(a[3]), "r"(b[0]), "r"(b[1]));
}

// SW128 swizzle (Swizzle<3,4,3>) on byte offsets within a 128B-row tile
__device__ __forceinline__ uint32_t swz(uint32_t o) { return o ^ ((o >> 3) & 0x70); }

// ----------------------------------------------------------------------------
// Prep kernels
// ----------------------------------------------------------------------------
#define NA (NDIM*NDIM)
#define NB (NDIM*MMID)
#define NC (MMID*NDIM)
__global__ void quantW(const float* __restrict__ A, const float* __restrict__ B,
                       const float* __restrict__ C,
                       __half* __restrict__ Aq, __half* __restrict__ Aq2,
                       __half* __restrict__ Bq, __half* __restrict__ Bq2,
                       __half* __restrict__ Cq)
{
    size_t i = ((size_t)blockIdx.x * blockDim.x + threadIdx.x) * 4;
    const float* in; __half *o1, *o2;
    if (i < NA)                { in = A + i;            o1 = Aq + i;  o2 = Aq2 + i; }
    else if (i < NA + NB)      { i -= NA; in = B + i;   o1 = Bq + i;  o2 = Bq2 + i; }
    else if (i < NA + NB + NC) { i -= NA + NB; in = C + i; o1 = Cq + i; o2 = nullptr; }
    else return;

    float4 v = *reinterpret_cast<const float4*>(in);
    float q0 = q8(v.x), q1 = q8(v.y), q2 = q8(v.z), q3 = q8(v.w);
    __half2 p0 = __floats2half2_rn(q0, q1);
    __half2 p1 = __floats2half2_rn(q2, q3);
    uint2 pk;
    pk.x = *reinterpret_cast<uint32_t*>(&p0);
    pk.y = *reinterpret_cast<uint32_t*>(&p1);
    *reinterpret_cast<uint2*>(o1) = pk;
    if (o2) {
        const float s = 0.015625f;  // 1/64, exact scaling
        __half2 s0 = __floats2half2_rn(q0 * s, q1 * s);
        __half2 s1 = __floats2half2_rn(q2 * s, q3 * s);
        uint2 sk;
        sk.x = *reinterpret_cast<uint32_t*>(&s0);
        sk.y = *reinterpret_cast<uint32_t*>(&s1);
        *reinterpret_cast<uint2*>(o2) = sk;
    }
}

// split fp32 -> plane1 = fp16(v) at [col], plane2 = fp16((v-plane1)*64) at [col+cols]
__global__ void splitk(const float* __restrict__ src, int cols, __half* __restrict__ dst) {
    size_t idx = (size_t)blockIdx.x * blockDim.x + threadIdx.x;
    size_t i4 = idx * 4;
    if (i4 >= (size_t)MDIM * cols) return;
    int row = (int)(i4 / cols);
    int col = (int)(i4 % cols);
    float4 v = *reinterpret_cast<const float4*>(src + i4);
    float f[4] = {v.x, v.y, v.z, v.w};
    __half h1[4], h2[4];
#pragma unroll
    for (int j = 0; j < 4; j++) {
        __half b1 = __float2half_rn(f[j]);
        float r1 = f[j] - __half2float(b1);   // exact in fp32
        h1[j] = b1;
        h2[j] = __float2half_rn(r1 * 64.0f);  // scaled into normal fp16 range
    }
    __half* d0 = dst + (size_t)row * KEFF + col;
    auto pack = [](__half* h) {
        __half2 p0(h[0], h[1]), p1(h[2], h[3]);
        uint2 r;
        r.x = *reinterpret_cast<uint32_t*>(&p0);
        r.y = *reinterpret_cast<uint32_t*>(&p1);
        return r;
    };
    *reinterpret_cast<uint2*>(d0)        = pack(h1);
    *reinterpret_cast<uint2*>(d0 + cols) = pack(h2);
}

// ----------------------------------------------------------------------------
// HMMA GEMM-NT, 128x64 CTA tile, BK=64, 4-stage single-chunk pipeline,
// double-buffered ldmatrix fragments WITH cross-chunk ks0 prefetch,
// 16-chunk HMMA chains flushed to fp32 master, statically unrolled.
// 8 warps: wm = wid&3 (4 x 32 rows), wn = wid>>2 (2 x 32 cols).
// MODE 0 (fused GEMM1): chunk c -> B segment
//   c in [ 0,32): Aq   col (c&31)*64, ld NDIM   (pairs x plane1)
//   c in [32,64): Aq2  col (c&31)*64, ld NDIM   (pairs x plane2)
//   c in [64,80): Bq   col (c&15)*64, ld MMID   (pairs u plane1)
//   c in [80,96): Bq2  col (c&15)*64, ld MMID   (pairs u plane2)
//   epilogue: q8 -> fp32 outp + fp16 aux
// MODE 1 (GEMM2): B = P0 col (c&31)*64, ld NDIM; epilogue q8 -> fp32 outp.
// nchunk must be a multiple of 16 (96 and 32 are).
// ----------------------------------------------------------------------------
#define NSTAGE 4
#define BKE 64
#define TILEM 128
#define TILEN 64
#define CHAIN 16
#define A_BYTES (TILEM * 128)                   // 16 KB
#define B_BYTES (TILEN * 128)                   //  8 KB
#define STAGE_BYTES (A_BYTES + B_BYTES)         // 24 KB
#define SMEM_SZ (NSTAGE * STAGE_BYTES)          // 96 KB

template <int MODE>
__global__ void __launch_bounds__(256, 2)
mma_gemm(const __half* __restrict__ Aop, int ldA, int nchunk,
         const __half* __restrict__ P0, const __half* __restrict__ P1,
         const __half* __restrict__ P2, const __half* __restrict__ P3,
         float* __restrict__ outp, __half* __restrict__ aux, int ldOut)
{
    extern __shared__ char smem[];
    const uint32_t sb = smem_u32(smem);
    const int tid  = threadIdx.x;
    const int lane = tid & 31;
    const int wid  = tid >> 5;
    const int wm   = wid & 3;    // 4 m-slices of 32
    const int wn   = wid >> 2;   // 2 n-slices of 32
    const int m0 = blockIdx.y * TILEM;
    const int n0 = blockIdx.x * TILEN;

    // A: 128 rows, 2 threads/row, 4 x 16B each.  B: 64 rows, 4 threads/row, 2 x 16B.
    const int alr  = tid >> 1;
    const int alc0 = (tid & 1) * 4;
    const int blr  = tid >> 2;
    const int blc0 = (tid & 3) * 2;

    auto load_chunk = [&](int c) {
        const uint32_t sA = sb + (c % NSTAGE) * STAGE_BYTES;
        const uint32_t sB = sA + A_BYTES;
        const __half* arow = Aop + (size_t)(m0 + alr) * ldA + c * BKE;
        const __half* bsrc; int ldB;
        if (MODE == 0) {
            if (c < 64) { bsrc = ((c < 32) ? P0 : P1) + (size_t)(c & 31) * BKE; ldB = NDIM; }
            else        { bsrc = ((c < 80) ? P2 : P3) + (size_t)(c & 15) * BKE; ldB = MMID; }
        } else {
            bsrc = P0 + (size_t)(c & 31) * BKE; ldB = NDIM;
        }
        const __half* brow = bsrc + (size_t)(n0 + blr) * ldB;
#pragma unroll
        for (int j = 0; j < 4; j++) {
            int c16 = alc0 + j;
            cp16(sA + swz(alr * 128 + c16 * 16), arow + c16 * 8);
        }
#pragma unroll
        for (int j = 0; j < 2; j++) {
            int c16 = blc0 + j;
            cp16(sB + swz(blr * 128 + c16 * 16), brow + c16 * 8);
        }
        cp_commit();
    };

    float mst[2][4][4];   // master fp32 accumulator (RN adds)
    float acc[2][4][4];   // HMMA chain accumulator (16-chunk chains)
#pragma unroll
    for (int i = 0; i < 2; i++)
#pragma unroll
        for (int j = 0; j < 4; j++)
#pragma unroll
            for (int k = 0; k < 4; k++) mst[i][j][k] = 0.0f;

    // fragment double buffers
    uint32_t af[2][2][4];   // [buf][mt][reg]
    uint32_t bf[2][2][4];   // [buf][np][reg]

    // per-thread ldsm base rows
    const int arow_lo = wm * 32 + ((lane >> 3) & 1) * 8 + (lane & 7);  // + mt*16
    const int aku_off = (lane >> 4);                                    // + ks*2
    const int brow_lo = wn * 32 + (lane >> 4) * 8 + (lane & 7);         // + np*16
    const int bku_off = ((lane >> 3) & 1);                              // + ks*2

    auto load_frags = [&](uint32_t sA, uint32_t sB, int ks, int buf) {
#pragma unroll
        for (int mt = 0; mt < 2; mt++) {
            int row = arow_lo + mt * 16;
            int ku  = ks * 2 + aku_off;
            ldsm4(af[buf][mt][0], af[buf][mt][1], af[buf][mt][2], af[buf][mt][3],
                  sA + swz(row * 128 + ku * 16));
        }
#pragma unroll
        for (int np = 0; np < 2; np++) {
            int row = brow_lo + np * 16;
            int ku  = ks * 2 + bku_off;
            ldsm4(bf[buf][np][0], bf[buf][np][1], bf[buf][np][2], bf[buf][np][3],
                  sB + swz(row * 128 + ku * 16));
        }
    };

    // prologue
    load_chunk(0);
    load_chunk(1);
    load_chunk(2);
    asm volatile("cp.async.wait_group 1;" ::: "memory");   // chunks 0,1 resident
    __syncthreads();
    {   // preload (chunk 0, ks0) into buf 0
        const uint32_t sA0 = sb + 0 * STAGE_BYTES;
        load_frags(sA0, sA0 + A_BYTES, 0, 0);
    }

    const int nouter = nchunk / CHAIN;
    for (int cb = 0; cb < nouter; cb++) {
        // start fresh HMMA chain (statically placed)
#pragma unroll
        for (int i = 0; i < 2; i++)
#pragma unroll
            for (int j = 0; j < 4; j++)
#pragma unroll
                for (int k = 0; k < 4; k++) acc[i][j][k] = 0.0f;

#pragma unroll
        for (int ci = 0; ci < CHAIN; ci++) {
            const int c = cb * CHAIN + ci;
            const int s = c % NSTAGE;

            if (cb > 0 || ci > 0) {
                // chunks c and c+1 resident & (after barrier) CTA-visible
                asm volatile("cp.async.wait_group 1;" ::: "memory");
                __syncthreads();
            }

            if (c + 3 < nchunk) load_chunk(c + 3);
            else                cp_commit();        // keep group accounting uniform

            const uint32_t sA = sb + s * STAGE_BYTES;
            const uint32_t sB = sA + A_BYTES;

            // buf (0) holds (c, ks0) on loop entry; MMAs issue immediately.
            // ks<3: prefetch (c, ks+1); ks==3: prefetch (c+1, ks0) — its stage
            // is resident (wait_group 1) and distinct from the stage being
            // written ((c+3)%4 == (c-1)%4 != (c+1)%4).
#pragma unroll
            for (int ks = 0; ks < 4; ks++) {
                const int cur = ks & 1, nxt = cur ^ 1;
                if (ks < 3) {
                    load_frags(sA, sB, ks + 1, nxt);
                } else if (c + 1 < nchunk) {
                    const uint32_t sA1 = sb + ((c + 1) % NSTAGE) * STAGE_BYTES;
                    load_frags(sA1, sA1 + A_BYTES, 0, nxt);
                }
#pragma unroll
                for (int mt = 0; mt < 2; mt++)
#pragma unroll
                    for (int nt = 0; nt < 4; nt++)
                        mma16816(acc[mt][nt], af[cur][mt], &bf[cur][nt >> 1][(nt & 1) * 2]);
            }
        }

        // flush chain into master (RN), statically placed
#pragma unroll
        for (int i = 0; i < 2; i++)
#pragma unroll
            for (int j = 0; j < 4; j++)
#pragma unroll
                for (int k = 0; k < 4; k++) mst[i][j][k] += acc[i][j][k];
    }

    // Epilogue: q8 then direct stores
#pragma unroll
    for (int mt = 0; mt < 2; mt++) {
#pragma unroll
        for (int nt = 0; nt < 4; nt++) {
            int row0 = m0 + wm * 32 + mt * 16 + (lane >> 2);
            int col  = n0 + wn * 32 + nt * 8 + 2 * (lane & 3);
#pragma unroll
            for (int h = 0; h < 2; h++) {
                int row = row0 + h * 8;
                float v0 = q8(mst[mt][nt][h * 2 + 0]);
                float v1 = q8(mst[mt][nt][h * 2 + 1]);
                size_t g = (size_t)row * ldOut + col;
                *reinterpret_cast<float2*>(outp + g) = make_float2(v0, v1);
                if (MODE == 0) {
                    __half2 hv = __floats2half2_rn(v0, v1);
                    *reinterpret_cast<__half2*>(aux + g) = hv;
                }
            }
        }
    }
}

// ----------------------------------------------------------------------------
// Host launcher
// Launch order (ncu capture lands on index 3 = mma_gemm<0>):
//   0: quantW   1: splitk(x)   2: splitk(u)   3: gemm1   4: gemm2
// ----------------------------------------------------------------------------
extern "C" void kernel_launch(void* const* d_in, const int* in_sizes, int n_in,
                              void* d_out, int out_size)
{
    const float* x = (const float*)d_in[0];
    const float* u = (const float*)d_in[1];
    const float* A = (const float*)d_in[2];
    const float* B = (const float*)d_in[3];
    const float* C = (const float*)d_in[4];

    float* x_next = (float*)d_out;
    float* y      = (float*)d_out + (size_t)MDIM * NDIM;

    __half *Aq, *Aq2, *Bq, *Bq2, *Cq, *XU, *Xn;
    cudaGetSymbolAddress((void**)&Aq,  g_Aq);
    cudaGetSymbolAddress((void**)&Aq2, g_Aq2);
    cudaGetSymbolAddress((void**)&Bq,  g_Bq);
    cudaGetSymbolAddress((void**)&Bq2, g_Bq2);
    cudaGetSymbolAddress((void**)&Cq,  g_Cq);
    cudaGetSymbolAddress((void**)&XU,  g_XU);
    cudaGetSymbolAddress((void**)&Xn,  g_Xn);

    cudaFuncSetAttribute(mma_gemm<0>, cudaFuncAttributeMaxDynamicSharedMemorySize, SMEM_SZ);
    cudaFuncSetAttribute(mma_gemm<1>, cudaFuncAttributeMaxDynamicSharedMemorySize, SMEM_SZ);

    const int T = 256;
    // 0: all weight quantization in one launch
    {
        int total4 = (NA + NB + NC) / 4;
        quantW<<<(total4 + T - 1) / T, T>>>(A, B, C, Aq, Aq2, Bq, Bq2, Cq);
    }
    // 1-2: activation splits
    splitk<<<(int)(((size_t)MDIM * NDIM / 4 + T - 1) / T), T>>>(x, NDIM, XU);
    splitk<<<(int)(((size_t)MDIM * MMID / 4 + T - 1) / T), T>>>(u, MMID, XU + 2 * NDIM);

    // 3: fused GEMM1: x_next = q8(XU @ [Aq | Aq/64 | Bq | Bq/64]^T), K=6144
    {
        dim3 grid(NDIM / TILEN, MDIM / TILEM);   // (32, 32)
        mma_gemm<0><<<grid, 256, SMEM_SZ>>>(
            XU, KEFF, KEFF / BKE,
            Aq, Aq2, Bq, Bq2,
            x_next, Xn, NDIM);
    }
    // 4: GEMM2: y = q8(Xn @ Cq^T), K=2048
    {
        dim3 grid(MMID / TILEN, MDIM / TILEM);   // (16, 32)
        mma_gemm<1><<<grid, 256, SMEM_SZ>>>(
            Xn, NDIM, NDIM / BKE,
            Cq, (const __half*)nullptr, (const __half*)nullptr, (const __half*)nullptr,
            y, (__half*)nullptr, MMID);
    }
}